// round 11
// baseline (speedup 1.0000x reference)
#include <cuda_runtime.h>
#include <cuda_bf16.h>
#include <cstdint>

// DynamicMaskHead: 128 instances, MLP 10 -> 8 -> 8 -> 1 over 160x160 px (fp32).
// Persistent barrier-free cp.async pipeline, 4 CTAs/SM, one wave (R8 skeleton).
// R9: weight LDS halved via paired LDS.128 (weights stored [o][k], duplicated
// float2 halves, consecutive k 16B-aligned); all 10 data LDS.128 front-batched.

#define NINST 128
#define CIN   10
#define CMID  8
#define HW    25600
#define HW4   (HW / 4)
#define TPB   128
#define TILE4 128                       // float4 per tile (512 px)
#define TILES_PER_INST 50
#define NSTAGE 2
#define NCTA 592                        // 4 per SM, one wave

#define SMEM_TILE_F4 (CIN * TILE4)      // 1280 float4 per stage (20 KB)
#define DYN_SMEM_BYTES (NSTAGE * SMEM_TILE_F4 * 16)   // 40960

__device__ __forceinline__ float2 ffma2(float2 a, float2 b, float2 c) {
    float2 d;
    asm("fma.rn.f32x2 %0, %1, %2, %3;"
        : "=l"(reinterpret_cast<unsigned long long&>(d))
        : "l"(reinterpret_cast<unsigned long long&>(a)),
          "l"(reinterpret_cast<unsigned long long&>(b)),
          "l"(reinterpret_cast<unsigned long long&>(c)));
    return d;
}

__device__ __forceinline__ float2 relu2(float2 a) {
    return make_float2(fmaxf(a.x, 0.0f), fmaxf(a.y, 0.0f));
}

__device__ __forceinline__ void cp16(uint32_t dst_smem, const float4* src) {
    asm volatile("cp.async.cg.shared.global [%0], [%1], 16;"
                 :: "r"(dst_smem), "l"(src));
}

__global__ void __launch_bounds__(TPB, 4)
mask_head_kernel(const float* __restrict__ feat,
                 const float* __restrict__ params,
                 float* __restrict__ out) {
    extern __shared__ float4 fbuf[];    // [NSTAGE][CIN][TILE4]

    // Double-buffered weight sets, duplicated float2 halves, 16B-aligned so
    // pairs of consecutive weights come back in one LDS.128.
    // w0s: [o][k] k=0..9 (o*10 even -> k even pairs aligned)
    // w1s: [o][k] k=0..7 ; w2s: [k] k=0..7
    __shared__ __align__(16) float2 w0s[2][CMID * CIN];
    __shared__ __align__(16) float2 w1s[2][CMID * CMID];
    __shared__ __align__(16) float2 w2s[2][CMID];
    __shared__ float2 b0s[2][CMID];
    __shared__ float2 b1s[2][CMID];
    __shared__ float2 b2s[2];

    const int tid = threadIdx.x;
    const int b   = blockIdx.x;

    // 6400 tiles over 592 CTAs: first 480 get 11, remaining 112 get 10.
    int first, count;
    if (b < 480) { first = b * 11;                count = 11; }
    else         { first = 5280 + (b - 480) * 10; count = 10; }

    const int inst0 = first / TILES_PER_INST;
    const int inst1 = (first + count - 1) / TILES_PER_INST;

    const float4* fin4 = reinterpret_cast<const float4*>(feat);
    float4* out4 = reinterpret_cast<float4*>(out);
    const uint32_t sbase = (uint32_t)__cvta_generic_to_shared(fbuf);

    auto issue_item = [&](int item, int stage) {
        const int inst = item / TILES_PER_INST;
        const int tile = item % TILES_PER_INST;
        const float4* g = fin4 + inst * CIN * HW4 + tile * TILE4 + tid;
        uint32_t s = sbase + (stage * SMEM_TILE_F4 + tid) * 16;
#pragma unroll
        for (int k = 0; k < CIN; k++) {
            cp16(s, g);
            g += HW4;
            s += TILE4 * 16;
        }
        asm volatile("cp.async.commit_group;");
    };

    int issued = 0;
    issue_item(first, 0); issued = 1;
    if (count > 1) { issue_item(first + 1, 1); issued = 2; }

    for (int i = tid; i < 169; i += TPB) {
        float va = params[inst0 * 169 + i];
        float vb = params[inst1 * 169 + i];
        float2 a2  = make_float2(va, va);
        float2 b2v = make_float2(vb, vb);
        if      (i < 80)  { w0s[0][i]       = a2; w0s[1][i]       = b2v; }
        else if (i < 144) { w1s[0][i - 80]  = a2; w1s[1][i - 80]  = b2v; }
        else if (i < 152) { w2s[0][i - 144] = a2; w2s[1][i - 144] = b2v; }
        else if (i < 160) { b0s[0][i - 152] = a2; b0s[1][i - 152] = b2v; }
        else if (i < 168) { b1s[0][i - 160] = a2; b1s[1][i - 160] = b2v; }
        else              { b2s[0]          = a2; b2s[1]          = b2v; }
    }
    __syncthreads();   // only block barrier in the kernel

    for (int i = 0; i < count; i++) {
        const int item = first + i;
        const int inst = item / TILES_PER_INST;
        const int tile = item % TILES_PER_INST;
        const int wsel = (inst != inst0) ? 1 : 0;
        const int stage = i & 1;

        if (issued > i + 1) asm volatile("cp.async.wait_group 1;");
        else                asm volatile("cp.async.wait_group 0;");

        const float4* sb = fbuf + stage * SMEM_TILE_F4 + tid;
        const float2* w0p = w0s[wsel];
        const float2* w1p = w1s[wsel];
        const float2* b0p = b0s[wsel];
        const float2* b1p = b1s[wsel];

        // ---- Front-batch all 10 data LDS.128 into registers ----
        float2 x[CIN][2];
#pragma unroll
        for (int k = 0; k < CIN; k++) {
            float4 v = sb[k * TILE4];
            x[k][0] = make_float2(v.x, v.y);
            x[k][1] = make_float2(v.z, v.w);
        }

        // ---- Layer 0 (10 -> 8, ReLU): paired weight LDS.128 over k ----
        float2 h0[CMID][2];
#pragma unroll
        for (int o = 0; o < CMID; o++) {
            float2 bb = b0p[o];
            h0[o][0] = bb; h0[o][1] = bb;
        }
#pragma unroll
        for (int o = 0; o < CMID; o++) {
            const float4* wrow = reinterpret_cast<const float4*>(w0p + o * CIN);
#pragma unroll
            for (int kp = 0; kp < CIN / 2; kp++) {      // 5 LDS.128 per o
                float4 wp = wrow[kp];
                float2 wlo = make_float2(wp.x, wp.y);
                float2 whi = make_float2(wp.z, wp.w);
                h0[o][0] = ffma2(wlo, x[2 * kp    ][0], h0[o][0]);
                h0[o][1] = ffma2(wlo, x[2 * kp    ][1], h0[o][1]);
                h0[o][0] = ffma2(whi, x[2 * kp + 1][0], h0[o][0]);
                h0[o][1] = ffma2(whi, x[2 * kp + 1][1], h0[o][1]);
            }
        }
#pragma unroll
        for (int o = 0; o < CMID; o++) {
            h0[o][0] = relu2(h0[o][0]);
            h0[o][1] = relu2(h0[o][1]);
        }

        // ---- Layers 1+2 fused, paired weight LDS.128 over k ----
        float2 acc0, acc1;
        {
            float2 bb = b2s[wsel];
            acc0 = bb; acc1 = bb;
        }
        const float4* w2row = reinterpret_cast<const float4*>(w2s[wsel]);
#pragma unroll
        for (int o = 0; o < CMID; o++) {
            float2 bb = b1p[o];
            float2 t0 = bb, t1 = bb;
            const float4* wrow = reinterpret_cast<const float4*>(w1p + o * CMID);
#pragma unroll
            for (int kp = 0; kp < CMID / 2; kp++) {     // 4 LDS.128 per o
                float4 wp = wrow[kp];
                float2 wlo = make_float2(wp.x, wp.y);
                float2 whi = make_float2(wp.z, wp.w);
                t0 = ffma2(wlo, h0[2 * kp    ][0], t0);
                t1 = ffma2(wlo, h0[2 * kp    ][1], t1);
                t0 = ffma2(whi, h0[2 * kp + 1][0], t0);
                t1 = ffma2(whi, h0[2 * kp + 1][1], t1);
            }
            // layer2 weight for outputs (o, o+1) fetched pairwise
            if ((o & 1) == 0) {
                float4 w2pair = w2row[o / 2];
                float2 w2lo = make_float2(w2pair.x, w2pair.y);
                acc0 = ffma2(w2lo, relu2(t0), acc0);
                acc1 = ffma2(w2lo, relu2(t1), acc1);
                // stash hi half for next o via registers
                // (handled below by recomputing pair on odd o)
            } else {
                float4 w2pair = w2row[o / 2];
                float2 w2hi = make_float2(w2pair.z, w2pair.w);
                acc0 = ffma2(w2hi, relu2(t0), acc0);
                acc1 = ffma2(w2hi, relu2(t1), acc1);
            }
        }

        out4[inst * HW4 + tile * TILE4 + tid] =
            make_float4(acc0.x, acc0.y, acc1.x, acc1.y);

        if (issued < count) { issue_item(first + issued, issued & 1); issued++; }
    }
}

extern "C" void kernel_launch(void* const* d_in, const int* in_sizes, int n_in,
                              void* d_out, int out_size) {
    const float* feat   = (const float*)d_in[0];
    const float* params = (const float*)d_in[1];
    float* out          = (float*)d_out;

    cudaFuncSetAttribute(mask_head_kernel,
                         cudaFuncAttributeMaxDynamicSharedMemorySize,
                         DYN_SMEM_BYTES);

    mask_head_kernel<<<NCTA, TPB, DYN_SMEM_BYTES>>>(feat, params, out);
}